// round 1
// baseline (speedup 1.0000x reference)
#include <cuda_runtime.h>
#include <cuda_bf16.h>
#include <math.h>

#define N_NODES   3000
#define HID       64
#define MAXD      128
#define NGRP      4
#define BATCH     256
#define SEQL      50

// ---------------- scratch (device globals; no allocation) ----------------
__device__ int   g_col[N_NODES * MAXD];
__device__ int   g_deg[N_NODES];
__device__ float g_a  [N_NODES * MAXD];
__device__ float g_q  [N_NODES * HID];
__device__ float g_k  [N_NODES * HID];
__device__ float g_v  [N_NODES * HID];
__device__ float g_z0 [N_NODES * HID];
__device__ float g_z1 [N_NODES * HID];
__device__ float g_h  [N_NODES * HID];
__device__ float g_ss2[N_NODES];
__device__ float g_P  [NGRP * HID + 1];   // [0..255]=P[g,h], [256]=sum(Wp)

// ---------------- 1. build CSR from dense adj ----------------
__global__ void build_csr(const float* __restrict__ adj) {
    int i = blockIdx.x;
    __shared__ int cnt;
    if (threadIdx.x == 0) cnt = 0;
    __syncthreads();
    const float4* row = reinterpret_cast<const float4*>(adj + (size_t)i * N_NODES);
    for (int j4 = threadIdx.x; j4 < N_NODES / 4; j4 += blockDim.x) {
        float4 f = row[j4];
        int j = j4 * 4;
        if (f.x > 0.f) { int p = atomicAdd(&cnt, 1); if (p < MAXD) g_col[i * MAXD + p] = j; }
        if (f.y > 0.f) { int p = atomicAdd(&cnt, 1); if (p < MAXD) g_col[i * MAXD + p] = j + 1; }
        if (f.z > 0.f) { int p = atomicAdd(&cnt, 1); if (p < MAXD) g_col[i * MAXD + p] = j + 2; }
        if (f.w > 0.f) { int p = atomicAdd(&cnt, 1); if (p < MAXD) g_col[i * MAXD + p] = j + 3; }
    }
    __syncthreads();
    if (threadIdx.x == 0) g_deg[i] = min(cnt, MAXD);
}

// ---------------- 2. q/k/v projections ----------------
// blockDim (64,8), each block handles 32 rows. Wq/Wk/Wv in smem (48KB exactly).
__global__ __launch_bounds__(512) void qkv_kernel(
    const float* __restrict__ h_ext, int hsel,
    const float* __restrict__ Wq, const float* __restrict__ Wk, const float* __restrict__ Wv)
{
    __shared__ float sW[3][HID * HID];
    const float* hsrc = (hsel == 0) ? h_ext : g_h;
    int tid = threadIdx.y * 64 + threadIdx.x;
    for (int idx = tid; idx < HID * HID; idx += 512) {
        sW[0][idx] = Wq[idx]; sW[1][idx] = Wk[idx]; sW[2][idx] = Wv[idx];
    }
    __syncthreads();
    int t = threadIdx.x;
    int row0 = blockIdx.x * 32;
    for (int rr = threadIdx.y; rr < 32; rr += 8) {
        int gi = row0 + rr;
        if (gi >= N_NODES) continue;
        float aq = 0.f, ak = 0.f, av = 0.f;
        const float* hp = hsrc + gi * HID;
#pragma unroll
        for (int c = 0; c < HID; c++) {
            float hv = __ldg(&hp[c]);          // warp-uniform -> broadcast
            aq += hv * sW[0][c * 64 + t];
            ak += hv * sW[1][c * 64 + t];
            av += hv * sW[2][c * 64 + t];
        }
        g_q[gi * HID + t] = aq;
        g_k[gi * HID + t] = ak;
        g_v[gi * HID + t] = av;
    }
}

// ---------------- 3. per-edge scores + row softmax (warp per row) ----------------
__global__ __launch_bounds__(256) void edge_softmax() {
    int warp = (blockIdx.x * blockDim.x + threadIdx.x) >> 5;
    int lane = threadIdx.x & 31;
    int wl = threadIdx.x >> 5;
    if (warp >= N_NODES) return;
    int i = warp;
    __shared__ __align__(16) float sq[8][HID];
    sq[wl][lane]      = g_q[i * HID + lane];
    sq[wl][lane + 32] = g_q[i * HID + lane + 32];
    __syncwarp();
    int deg = g_deg[i];
    const float4* q4 = reinterpret_cast<const float4*>(sq[wl]);
    float vals[4];
#pragma unroll
    for (int tpass = 0; tpass < 4; tpass++) {
        int s = lane + 32 * tpass;
        float d = -1e30f;
        if (s < deg) {
            int j = g_col[i * MAXD + s];
            const float4* k4 = reinterpret_cast<const float4*>(&g_k[j * HID]);
            float acc = 0.f;
#pragma unroll
            for (int c4 = 0; c4 < HID / 4; c4++) {
                float4 kk = __ldg(&k4[c4]);
                float4 qq = q4[c4];
                acc += qq.x * kk.x + qq.y * kk.y + qq.z * kk.z + qq.w * kk.w;
            }
            d = acc * 0.125f;    // 1/sqrt(64)
        }
        vals[tpass] = d;
    }
    float m = fmaxf(fmaxf(vals[0], vals[1]), fmaxf(vals[2], vals[3]));
#pragma unroll
    for (int o = 16; o > 0; o >>= 1) m = fmaxf(m, __shfl_xor_sync(0xffffffffu, m, o));
    float sum = 0.f;
#pragma unroll
    for (int tpass = 0; tpass < 4; tpass++) {
        int s = lane + 32 * tpass;
        float e = (s < deg) ? __expf(vals[tpass] - m) : 0.f;
        vals[tpass] = e;
        sum += e;
    }
#pragma unroll
    for (int o = 16; o > 0; o >>= 1) sum += __shfl_xor_sync(0xffffffffu, sum, o);
    float inv = 1.f / sum;
#pragma unroll
    for (int tpass = 0; tpass < 4; tpass++) {
        int s = lane + 32 * tpass;
        if (s < deg) g_a[i * MAXD + s] = vals[tpass] * inv;
    }
}

// ---------------- 4. SpMM hop: out = 0.85*A@zin + 0.15*v (+ residual) ----------------
// blockDim (64,4). sel: 0=g_z0, 1=g_z1, 2=g_v. resid_sel: 0=none, 1=ext ptr, 2=g_h
__global__ __launch_bounds__(256) void spmm_kernel(
    int zin_sel, int out_sel, int resid_sel, const float* __restrict__ resid_ext)
{
    int i = blockIdx.x * blockDim.y + threadIdx.y;
    if (i >= N_NODES) return;
    const float* zin = (zin_sel == 0) ? g_z0 : (zin_sel == 1) ? g_z1 : g_v;
    float* outp      = (out_sel == 0) ? g_z0 : (out_sel == 1) ? g_z1 : g_h;
    int h = threadIdx.x;
    int deg = g_deg[i];
    const int*   cp = &g_col[i * MAXD];
    const float* ap = &g_a  [i * MAXD];
    float acc = 0.f;
    int s = 0;
    for (; s + 4 <= deg; s += 4) {
        int j0 = cp[s], j1 = cp[s + 1], j2 = cp[s + 2], j3 = cp[s + 3];
        float a0 = ap[s], a1 = ap[s + 1], a2 = ap[s + 2], a3 = ap[s + 3];
        acc += a0 * zin[j0 * HID + h];
        acc += a1 * zin[j1 * HID + h];
        acc += a2 * zin[j2 * HID + h];
        acc += a3 * zin[j3 * HID + h];
    }
    for (; s < deg; s++) acc += ap[s] * zin[cp[s] * HID + h];
    float r = 0.85f * acc + 0.15f * g_v[i * HID + h];
    if (resid_sel == 1) r += resid_ext[i * HID + h];
    else if (resid_sel == 2) r += g_h[i * HID + h];
    outp[i * HID + h] = r;
}

// ---------------- 5a. zero accumulators ----------------
__global__ void init_p() {
    int t = threadIdx.x;
    if (t <= NGRP * HID) g_P[t] = 0.f;
}

// ---------------- 5b. cluster softmax, ss2, P[g,h], sum(Wp) ----------------
__global__ __launch_bounds__(256) void cluster_kernel(
    const float* __restrict__ Wg, const float* __restrict__ bg, const float* __restrict__ Wp)
{
    __shared__ float sWg[HID * NGRP];
    __shared__ float sbg[NGRP];
    __shared__ float sws[256 * NGRP];
    __shared__ float sred[256];
    int tid = threadIdx.x;
    if (tid < HID * NGRP) sWg[tid] = Wg[tid];
    if (tid < NGRP) sbg[tid] = bg[tid];
    __syncthreads();
    int base = blockIdx.x * 256;
    int n = base + tid;
    float wpv = 0.f, s0 = 0.f, s1 = 0.f, s2 = 0.f, s3 = 0.f;
    if (n < N_NODES) {
        float l0 = sbg[0], l1 = sbg[1], l2 = sbg[2], l3 = sbg[3];
#pragma unroll
        for (int c = 0; c < HID; c++) {
            float hv = g_h[n * HID + c];
            l0 += hv * sWg[c * 4 + 0];
            l1 += hv * sWg[c * 4 + 1];
            l2 += hv * sWg[c * 4 + 2];
            l3 += hv * sWg[c * 4 + 3];
        }
        float m = fmaxf(fmaxf(l0, l1), fmaxf(l2, l3));
        float e0 = __expf(l0 - m), e1 = __expf(l1 - m), e2 = __expf(l2 - m), e3 = __expf(l3 - m);
        float inv = 1.f / (e0 + e1 + e2 + e3);
        s0 = e0 * inv; s1 = e1 * inv; s2 = e2 * inv; s3 = e3 * inv;
        g_ss2[n] = s0 * s0 + s1 * s1 + s2 * s2 + s3 * s3;
        wpv = Wp[n];
    }
    sws[tid * 4 + 0] = s0 * wpv;
    sws[tid * 4 + 1] = s1 * wpv;
    sws[tid * 4 + 2] = s2 * wpv;
    sws[tid * 4 + 3] = s3 * wpv;
    sred[tid] = wpv;
    __syncthreads();
    int g = tid >> 6, h = tid & 63;
    int nv = min(256, N_NODES - base);
    float acc = 0.f;
    for (int nn = 0; nn < nv; nn++)
        acc += sws[nn * 4 + g] * g_h[(base + nn) * HID + h];
    atomicAdd(&g_P[g * HID + h], acc);
    for (int s = 128; s > 0; s >>= 1) {
        __syncthreads();
        if (tid < s) sred[tid] += sred[tid + s];
    }
    __syncthreads();
    if (tid == 0) atomicAdd(&g_P[NGRP * HID], sred[0]);
}

// ---------------- 6. per-user stats + fused epilogue ----------------
__global__ __launch_bounds__(64) void finalize_kernel(
    const int* __restrict__ cate, const float* __restrict__ gamma,
    const float* __restrict__ beta, const float* __restrict__ bp, float* __restrict__ out)
{
    int b = blockIdx.x;
    int h = threadIdx.x;
    float S1 = 0.f, S2 = 0.f;
#pragma unroll 1
    for (int l = 0; l < SEQL; l++) {
        int c = cate[b * SEQL + l];
        if (c != 0) {
            float gv = g_h[c * HID + h];
            S1 += gv;                      // sum_g s[c,g] == 1
            S2 += gv * gv * g_ss2[c];
        }
    }
    const float invn = 1.f / (float)(NGRP * SEQL);
    float mean = S1 * invn;
    float var  = S2 * invn - mean * mean;
    float inv  = rsqrtf(var + 1e-5f);
    float ga = gamma[h], be = beta[h];
    float Swp = g_P[NGRP * HID];
    float bpv = bp[0];
    float k1 = inv * ga;
    float addc = be * Swp + bpv;
    float ms = mean * Swp;
#pragma unroll
    for (int g = 0; g < NGRP; g++) {
        out[(b * NGRP + g) * HID + h] = k1 * (g_P[g * HID + h] - ms) + addc;
    }
}

// ---------------- launch ----------------
extern "C" void kernel_launch(void* const* d_in, const int* in_sizes, int n_in,
                              void* d_out, int out_size)
{
    const int*   cate  = (const int*)  d_in[0];
    const float* adj   = (const float*)d_in[1];
    const float* emb   = (const float*)d_in[2];
    const float* Wq    = (const float*)d_in[3];
    const float* Wk    = (const float*)d_in[4];
    const float* Wv    = (const float*)d_in[5];
    const float* Wg    = (const float*)d_in[6];
    const float* bg    = (const float*)d_in[7];
    const float* Wp    = (const float*)d_in[8];
    const float* bp    = (const float*)d_in[9];
    const float* gamma = (const float*)d_in[10];
    const float* beta  = (const float*)d_in[11];
    float* out = (float*)d_out;

    build_csr<<<N_NODES, 128>>>(adj);

    for (int l = 0; l < 2; l++) {
        qkv_kernel<<<(N_NODES + 31) / 32, dim3(64, 8)>>>(
            emb, (l == 0) ? 0 : 1, Wq + l * HID * HID, Wk + l * HID * HID, Wv + l * HID * HID);
        edge_softmax<<<(N_NODES * 32 + 255) / 256, 256>>>();
        // z = v; 4 hops; last hop fused with residual into g_h
        spmm_kernel<<<(N_NODES + 3) / 4, dim3(64, 4)>>>(2, 0, 0, nullptr);           // z0 = f(v)
        spmm_kernel<<<(N_NODES + 3) / 4, dim3(64, 4)>>>(0, 1, 0, nullptr);           // z1 = f(z0)
        spmm_kernel<<<(N_NODES + 3) / 4, dim3(64, 4)>>>(1, 0, 0, nullptr);           // z0 = f(z1)
        spmm_kernel<<<(N_NODES + 3) / 4, dim3(64, 4)>>>(0, 2, (l == 0) ? 1 : 2,
                                                        (l == 0) ? emb : nullptr);   // h = resid + f(z0)
    }

    init_p<<<1, NGRP * HID + 1>>>();
    cluster_kernel<<<(N_NODES + 255) / 256, 256>>>(Wg, bg, Wp);
    finalize_kernel<<<BATCH, HID>>>(cate, gamma, beta, bp, out);
}

// round 3
// speedup vs baseline: 1.0171x; 1.0171x over previous
#include <cuda_runtime.h>
#include <cuda_bf16.h>
#include <math.h>

#define N_NODES   3000
#define HID       64
#define MAXD      128
#define NGRP      4
#define BATCH     256
#define SEQL      50

// ---------------- scratch (device globals; no allocation) ----------------
__device__ int   g_col[N_NODES * MAXD];
__device__ int   g_deg[N_NODES];     // real degree
__device__ int   g_degp[N_NODES];    // padded to multiple of 8
__device__ float g_a  [N_NODES * MAXD];
__device__ float g_q  [N_NODES * HID];
__device__ float g_k  [N_NODES * HID];
__device__ float g_v  [N_NODES * HID];
__device__ float g_z0 [N_NODES * HID];
__device__ float g_z1 [N_NODES * HID];
__device__ float g_h  [N_NODES * HID];
__device__ float g_ss2[N_NODES];
__device__ float g_P  [NGRP * HID + 1];   // [0..255]=P[g,h], [256]=sum(Wp)

// ---------------- 1. build CSR from dense adj (+ zero g_P for this replay) ----------------
__global__ void build_csr(const float* __restrict__ adj) {
    int i = blockIdx.x;
    // zero the epilogue accumulator each replay (ALL 257 entries, strided)
    if (i == 0) {
        for (int t = threadIdx.x; t <= NGRP * HID; t += blockDim.x) g_P[t] = 0.f;
    }
    __shared__ int cnt;
    if (threadIdx.x == 0) cnt = 0;
    __syncthreads();
    const float4* row = reinterpret_cast<const float4*>(adj + (size_t)i * N_NODES);
    for (int j4 = threadIdx.x; j4 < N_NODES / 4; j4 += blockDim.x) {
        float4 f = row[j4];
        int j = j4 * 4;
        if (f.x > 0.f) { int p = atomicAdd(&cnt, 1); if (p < MAXD) g_col[i * MAXD + p] = j; }
        if (f.y > 0.f) { int p = atomicAdd(&cnt, 1); if (p < MAXD) g_col[i * MAXD + p] = j + 1; }
        if (f.z > 0.f) { int p = atomicAdd(&cnt, 1); if (p < MAXD) g_col[i * MAXD + p] = j + 2; }
        if (f.w > 0.f) { int p = atomicAdd(&cnt, 1); if (p < MAXD) g_col[i * MAXD + p] = j + 3; }
    }
    __syncthreads();
    int deg = min(cnt, MAXD);
    int degp = min((deg + 7) & ~7, MAXD);
    if (threadIdx.x == 0) { g_deg[i] = deg; g_degp[i] = degp; }
    // deterministic padding columns
    for (int p = deg + (int)threadIdx.x; p < degp; p += blockDim.x) g_col[i * MAXD + p] = 0;
}

// ---------------- 2. q/k/v projections ----------------
__global__ __launch_bounds__(512) void qkv_kernel(
    const float* __restrict__ h_ext, int hsel,
    const float* __restrict__ Wq, const float* __restrict__ Wk, const float* __restrict__ Wv)
{
    __shared__ float sW[3][HID * HID];
    const float* hsrc = (hsel == 0) ? h_ext : g_h;
    int tid = threadIdx.y * 64 + threadIdx.x;
    for (int idx = tid; idx < HID * HID; idx += 512) {
        sW[0][idx] = Wq[idx]; sW[1][idx] = Wk[idx]; sW[2][idx] = Wv[idx];
    }
    __syncthreads();
    int t = threadIdx.x;
    int row0 = blockIdx.x * 32;
    for (int rr = threadIdx.y; rr < 32; rr += 8) {
        int gi = row0 + rr;
        if (gi >= N_NODES) continue;
        float aq = 0.f, ak = 0.f, av = 0.f;
        const float* hp = hsrc + gi * HID;
#pragma unroll
        for (int c = 0; c < HID; c++) {
            float hv = __ldg(&hp[c]);
            aq += hv * sW[0][c * 64 + t];
            ak += hv * sW[1][c * 64 + t];
            av += hv * sW[2][c * 64 + t];
        }
        g_q[gi * HID + t] = aq;
        g_k[gi * HID + t] = ak;
        g_v[gi * HID + t] = av;
    }
}

// ---------------- 3. per-edge scores + row softmax (warp per row) ----------------
__global__ __launch_bounds__(256) void edge_softmax() {
    int warp = (blockIdx.x * blockDim.x + threadIdx.x) >> 5;
    int lane = threadIdx.x & 31;
    int wl = threadIdx.x >> 5;
    if (warp >= N_NODES) return;
    int i = warp;
    __shared__ __align__(16) float sq[8][HID];
    sq[wl][lane]      = g_q[i * HID + lane];
    sq[wl][lane + 32] = g_q[i * HID + lane + 32];
    __syncwarp();
    int deg = g_deg[i];
    int degp = g_degp[i];
    const float4* q4 = reinterpret_cast<const float4*>(sq[wl]);
    float vals[4];
#pragma unroll
    for (int tpass = 0; tpass < 4; tpass++) {
        int s = lane + 32 * tpass;
        float d = -1e30f;
        if (s < deg) {
            int j = g_col[i * MAXD + s];
            const float4* k4 = reinterpret_cast<const float4*>(&g_k[j * HID]);
            float acc = 0.f;
#pragma unroll
            for (int c4 = 0; c4 < HID / 4; c4++) {
                float4 kk = __ldg(&k4[c4]);
                float4 qq = q4[c4];
                acc += qq.x * kk.x + qq.y * kk.y + qq.z * kk.z + qq.w * kk.w;
            }
            d = acc * 0.125f;    // 1/sqrt(64)
        }
        vals[tpass] = d;
    }
    float m = fmaxf(fmaxf(vals[0], vals[1]), fmaxf(vals[2], vals[3]));
#pragma unroll
    for (int o = 16; o > 0; o >>= 1) m = fmaxf(m, __shfl_xor_sync(0xffffffffu, m, o));
    float sum = 0.f;
#pragma unroll
    for (int tpass = 0; tpass < 4; tpass++) {
        int s = lane + 32 * tpass;
        float e = (s < deg) ? __expf(vals[tpass] - m) : 0.f;
        vals[tpass] = e;
        sum += e;
    }
#pragma unroll
    for (int o = 16; o > 0; o >>= 1) sum += __shfl_xor_sync(0xffffffffu, sum, o);
    float inv = 1.f / sum;
#pragma unroll
    for (int tpass = 0; tpass < 4; tpass++) {
        int s = lane + 32 * tpass;
        if (s < deg) g_a[i * MAXD + s] = vals[tpass] * inv;
        else if (s < degp) g_a[i * MAXD + s] = 0.f;    // zero the padding coefs
    }
}

// ---------------- 4. SpMM hop: out = 0.85*A@zin + 0.15*v (+ residual) ----------------
// blockDim (64,2). Padded-degree 8-wide batches, two accumulators.
__global__ __launch_bounds__(128) void spmm_kernel(
    int zin_sel, int out_sel, int resid_sel, const float* __restrict__ resid_ext)
{
    int i = blockIdx.x * 2 + threadIdx.y;
    if (i >= N_NODES) return;
    const float* __restrict__ zin = (zin_sel == 0) ? g_z0 : (zin_sel == 1) ? g_z1 : g_v;
    float* __restrict__ outp      = (out_sel == 0) ? g_z0 : (out_sel == 1) ? g_z1 : g_h;
    int h = threadIdx.x;
    int degp = g_degp[i];
    const int*   __restrict__ cp = &g_col[i * MAXD];
    const float* __restrict__ ap = &g_a  [i * MAXD];
    float acc0 = 0.f, acc1 = 0.f;
    for (int s = 0; s < degp; s += 8) {
        int   j0 = __ldg(&cp[s]),     j1 = __ldg(&cp[s + 1]),
              j2 = __ldg(&cp[s + 2]), j3 = __ldg(&cp[s + 3]),
              j4 = __ldg(&cp[s + 4]), j5 = __ldg(&cp[s + 5]),
              j6 = __ldg(&cp[s + 6]), j7 = __ldg(&cp[s + 7]);
        float a0 = __ldg(&ap[s]),     a1 = __ldg(&ap[s + 1]),
              a2 = __ldg(&ap[s + 2]), a3 = __ldg(&ap[s + 3]),
              a4 = __ldg(&ap[s + 4]), a5 = __ldg(&ap[s + 5]),
              a6 = __ldg(&ap[s + 6]), a7 = __ldg(&ap[s + 7]);
        float z0 = __ldg(&zin[j0 * HID + h]);
        float z1 = __ldg(&zin[j1 * HID + h]);
        float z2 = __ldg(&zin[j2 * HID + h]);
        float z3 = __ldg(&zin[j3 * HID + h]);
        float z4 = __ldg(&zin[j4 * HID + h]);
        float z5 = __ldg(&zin[j5 * HID + h]);
        float z6 = __ldg(&zin[j6 * HID + h]);
        float z7 = __ldg(&zin[j7 * HID + h]);
        acc0 += a0 * z0; acc1 += a1 * z1;
        acc0 += a2 * z2; acc1 += a3 * z3;
        acc0 += a4 * z4; acc1 += a5 * z5;
        acc0 += a6 * z6; acc1 += a7 * z7;
    }
    float r = 0.85f * (acc0 + acc1) + 0.15f * g_v[i * HID + h];
    if (resid_sel == 1) r += resid_ext[i * HID + h];
    else if (resid_sel == 2) r += g_h[i * HID + h];
    outp[i * HID + h] = r;
}

// ---------------- 5. cluster softmax, ss2, P[g,h], sum(Wp) ----------------
__global__ __launch_bounds__(256) void cluster_kernel(
    const float* __restrict__ Wg, const float* __restrict__ bg, const float* __restrict__ Wp)
{
    __shared__ float sWg[HID * NGRP];
    __shared__ float sbg[NGRP];
    __shared__ float sws[256 * NGRP];
    __shared__ float sred[256];
    int tid = threadIdx.x;
    if (tid < HID * NGRP) sWg[tid] = Wg[tid];
    if (tid < NGRP) sbg[tid] = bg[tid];
    __syncthreads();
    int base = blockIdx.x * 256;
    int n = base + tid;
    float wpv = 0.f, s0 = 0.f, s1 = 0.f, s2 = 0.f, s3 = 0.f;
    if (n < N_NODES) {
        float l0 = sbg[0], l1 = sbg[1], l2 = sbg[2], l3 = sbg[3];
#pragma unroll
        for (int c = 0; c < HID; c++) {
            float hv = g_h[n * HID + c];
            l0 += hv * sWg[c * 4 + 0];
            l1 += hv * sWg[c * 4 + 1];
            l2 += hv * sWg[c * 4 + 2];
            l3 += hv * sWg[c * 4 + 3];
        }
        float m = fmaxf(fmaxf(l0, l1), fmaxf(l2, l3));
        float e0 = __expf(l0 - m), e1 = __expf(l1 - m), e2 = __expf(l2 - m), e3 = __expf(l3 - m);
        float inv = 1.f / (e0 + e1 + e2 + e3);
        s0 = e0 * inv; s1 = e1 * inv; s2 = e2 * inv; s3 = e3 * inv;
        g_ss2[n] = s0 * s0 + s1 * s1 + s2 * s2 + s3 * s3;
        wpv = Wp[n];
    }
    sws[tid * 4 + 0] = s0 * wpv;
    sws[tid * 4 + 1] = s1 * wpv;
    sws[tid * 4 + 2] = s2 * wpv;
    sws[tid * 4 + 3] = s3 * wpv;
    sred[tid] = wpv;
    __syncthreads();
    int g = tid >> 6, h = tid & 63;
    int nv = min(256, N_NODES - base);
    float acc = 0.f;
    for (int nn = 0; nn < nv; nn++)
        acc += sws[nn * 4 + g] * g_h[(base + nn) * HID + h];
    atomicAdd(&g_P[g * HID + h], acc);
    for (int s = 128; s > 0; s >>= 1) {
        __syncthreads();
        if (tid < s) sred[tid] += sred[tid + s];
    }
    __syncthreads();
    if (tid == 0) atomicAdd(&g_P[NGRP * HID], sred[0]);
}

// ---------------- 6. per-user stats + fused epilogue ----------------
__global__ __launch_bounds__(64) void finalize_kernel(
    const int* __restrict__ cate, const float* __restrict__ gamma,
    const float* __restrict__ beta, const float* __restrict__ bp, float* __restrict__ out)
{
    int b = blockIdx.x;
    int h = threadIdx.x;
    float S1 = 0.f, S2 = 0.f;
#pragma unroll 1
    for (int l = 0; l < SEQL; l++) {
        int c = cate[b * SEQL + l];
        if (c != 0) {
            float gv = g_h[c * HID + h];
            S1 += gv;                      // sum_g s[c,g] == 1
            S2 += gv * gv * g_ss2[c];
        }
    }
    const float invn = 1.f / (float)(NGRP * SEQL);
    float mean = S1 * invn;
    float var  = S2 * invn - mean * mean;
    float inv  = rsqrtf(var + 1e-5f);
    float ga = gamma[h], be = beta[h];
    float Swp = g_P[NGRP * HID];
    float bpv = bp[0];
    float k1 = inv * ga;
    float addc = be * Swp + bpv;
    float ms = mean * Swp;
#pragma unroll
    for (int g = 0; g < NGRP; g++) {
        out[(b * NGRP + g) * HID + h] = k1 * (g_P[g * HID + h] - ms) + addc;
    }
}

// ---------------- launch ----------------
extern "C" void kernel_launch(void* const* d_in, const int* in_sizes, int n_in,
                              void* d_out, int out_size)
{
    const int*   cate  = (const int*)  d_in[0];
    const float* adj   = (const float*)d_in[1];
    const float* emb   = (const float*)d_in[2];
    const float* Wq    = (const float*)d_in[3];
    const float* Wk    = (const float*)d_in[4];
    const float* Wv    = (const float*)d_in[5];
    const float* Wg    = (const float*)d_in[6];
    const float* bg    = (const float*)d_in[7];
    const float* Wp    = (const float*)d_in[8];
    const float* bp    = (const float*)d_in[9];
    const float* gamma = (const float*)d_in[10];
    const float* beta  = (const float*)d_in[11];
    float* out = (float*)d_out;

    build_csr<<<N_NODES, 128>>>(adj);

    for (int l = 0; l < 2; l++) {
        qkv_kernel<<<(N_NODES + 31) / 32, dim3(64, 8)>>>(
            emb, (l == 0) ? 0 : 1, Wq + l * HID * HID, Wk + l * HID * HID, Wv + l * HID * HID);
        edge_softmax<<<(N_NODES * 32 + 255) / 256, 256>>>();
        spmm_kernel<<<(N_NODES + 1) / 2, dim3(64, 2)>>>(2, 0, 0, nullptr);           // z0 = f(v)
        spmm_kernel<<<(N_NODES + 1) / 2, dim3(64, 2)>>>(0, 1, 0, nullptr);           // z1 = f(z0)
        spmm_kernel<<<(N_NODES + 1) / 2, dim3(64, 2)>>>(1, 0, 0, nullptr);           // z0 = f(z1)
        spmm_kernel<<<(N_NODES + 1) / 2, dim3(64, 2)>>>(0, 2, (l == 0) ? 1 : 2,
                                                        (l == 0) ? emb : nullptr);   // h = resid + f(z0)
    }

    cluster_kernel<<<(N_NODES + 255) / 256, 256>>>(Wg, bg, Wp);
    finalize_kernel<<<BATCH, HID>>>(cate, gamma, beta, bp, out);
}

// round 4
// speedup vs baseline: 1.1057x; 1.0871x over previous
#include <cuda_runtime.h>
#include <cuda_bf16.h>
#include <math.h>

#define N_NODES   3000
#define HID       64
#define MAXD      128
#define NGRP      4
#define BATCH     256
#define SEQL      50

// ---------------- scratch (device globals; no allocation) ----------------
__device__ int   g_col[N_NODES * MAXD];
__device__ int   g_deg[N_NODES];     // real degree
__device__ int   g_degp[N_NODES];    // padded to multiple of 8
__device__ __align__(16) float2 g_ca[N_NODES * MAXD];  // {.x=bitcast(col*HID), .y=coef}
__device__ float g_q  [N_NODES * HID];
__device__ float g_k  [N_NODES * HID];
__device__ float g_v  [N_NODES * HID];
__device__ float g_z0 [N_NODES * HID];
__device__ float g_z1 [N_NODES * HID];
__device__ float g_h  [N_NODES * HID];
__device__ float g_ss2[N_NODES];
__device__ float g_P  [NGRP * HID + 1];   // [0..255]=P[g,h], [256]=sum(Wp)

// ---------------- 1. build CSR from dense adj (+ zero g_P for this replay) ----------------
__global__ void build_csr(const float* __restrict__ adj) {
    int i = blockIdx.x;
    if (i == 0) {
        for (int t = threadIdx.x; t <= NGRP * HID; t += blockDim.x) g_P[t] = 0.f;
    }
    __shared__ int cnt;
    if (threadIdx.x == 0) cnt = 0;
    __syncthreads();
    const float4* row = reinterpret_cast<const float4*>(adj + (size_t)i * N_NODES);
    for (int j4 = threadIdx.x; j4 < N_NODES / 4; j4 += blockDim.x) {
        float4 f = row[j4];
        int j = j4 * 4;
        if (f.x > 0.f) { int p = atomicAdd(&cnt, 1); if (p < MAXD) g_col[i * MAXD + p] = j; }
        if (f.y > 0.f) { int p = atomicAdd(&cnt, 1); if (p < MAXD) g_col[i * MAXD + p] = j + 1; }
        if (f.z > 0.f) { int p = atomicAdd(&cnt, 1); if (p < MAXD) g_col[i * MAXD + p] = j + 2; }
        if (f.w > 0.f) { int p = atomicAdd(&cnt, 1); if (p < MAXD) g_col[i * MAXD + p] = j + 3; }
    }
    __syncthreads();
    int deg = min(cnt, MAXD);
    int degp = min((deg + 7) & ~7, MAXD);
    if (threadIdx.x == 0) { g_deg[i] = deg; g_degp[i] = degp; }
    for (int p = deg + (int)threadIdx.x; p < degp; p += blockDim.x) g_col[i * MAXD + p] = 0;
}

// ---------------- 2. q/k/v projections ----------------
__global__ __launch_bounds__(512) void qkv_kernel(
    const float* __restrict__ h_ext, int hsel,
    const float* __restrict__ Wq, const float* __restrict__ Wk, const float* __restrict__ Wv)
{
    __shared__ float sW[3][HID * HID];
    const float* hsrc = (hsel == 0) ? h_ext : g_h;
    int tid = threadIdx.y * 64 + threadIdx.x;
    for (int idx = tid; idx < HID * HID; idx += 512) {
        sW[0][idx] = Wq[idx]; sW[1][idx] = Wk[idx]; sW[2][idx] = Wv[idx];
    }
    __syncthreads();
    int t = threadIdx.x;
    int row0 = blockIdx.x * 32;
    for (int rr = threadIdx.y; rr < 32; rr += 8) {
        int gi = row0 + rr;
        if (gi >= N_NODES) continue;
        float aq = 0.f, ak = 0.f, av = 0.f;
        const float* hp = hsrc + gi * HID;
#pragma unroll
        for (int c = 0; c < HID; c++) {
            float hv = __ldg(&hp[c]);
            aq += hv * sW[0][c * 64 + t];
            ak += hv * sW[1][c * 64 + t];
            av += hv * sW[2][c * 64 + t];
        }
        g_q[gi * HID + t] = aq;
        g_k[gi * HID + t] = ak;
        g_v[gi * HID + t] = av;
    }
}

// ---------------- 3. per-edge scores + row softmax (warp per row) ----------------
// Writes packed {col*HID, coef} float2 per edge (zero coef on padding).
__global__ __launch_bounds__(256) void edge_softmax() {
    int warp = (blockIdx.x * blockDim.x + threadIdx.x) >> 5;
    int lane = threadIdx.x & 31;
    int wl = threadIdx.x >> 5;
    if (warp >= N_NODES) return;
    int i = warp;
    __shared__ __align__(16) float sq[8][HID];
    sq[wl][lane]      = g_q[i * HID + lane];
    sq[wl][lane + 32] = g_q[i * HID + lane + 32];
    __syncwarp();
    int deg = g_deg[i];
    int degp = g_degp[i];
    const float4* q4 = reinterpret_cast<const float4*>(sq[wl]);
    float vals[4];
    int   cols[4];
#pragma unroll
    for (int tpass = 0; tpass < 4; tpass++) {
        int s = lane + 32 * tpass;
        float d = -1e30f;
        int j = 0;
        if (s < deg) {
            j = g_col[i * MAXD + s];
            const float4* k4 = reinterpret_cast<const float4*>(&g_k[j * HID]);
            float acc = 0.f;
#pragma unroll
            for (int c4 = 0; c4 < HID / 4; c4++) {
                float4 kk = __ldg(&k4[c4]);
                float4 qq = q4[c4];
                acc += qq.x * kk.x + qq.y * kk.y + qq.z * kk.z + qq.w * kk.w;
            }
            d = acc * 0.125f;    // 1/sqrt(64)
        }
        vals[tpass] = d;
        cols[tpass] = j;
    }
    float m = fmaxf(fmaxf(vals[0], vals[1]), fmaxf(vals[2], vals[3]));
#pragma unroll
    for (int o = 16; o > 0; o >>= 1) m = fmaxf(m, __shfl_xor_sync(0xffffffffu, m, o));
    float sum = 0.f;
#pragma unroll
    for (int tpass = 0; tpass < 4; tpass++) {
        int s = lane + 32 * tpass;
        float e = (s < deg) ? __expf(vals[tpass] - m) : 0.f;
        vals[tpass] = e;
        sum += e;
    }
#pragma unroll
    for (int o = 16; o > 0; o >>= 1) sum += __shfl_xor_sync(0xffffffffu, sum, o);
    float inv = 1.f / sum;
#pragma unroll
    for (int tpass = 0; tpass < 4; tpass++) {
        int s = lane + 32 * tpass;
        if (s < deg)
            g_ca[i * MAXD + s] = make_float2(__int_as_float(cols[tpass] * HID), vals[tpass] * inv);
        else if (s < degp)
            g_ca[i * MAXD + s] = make_float2(__int_as_float(0), 0.f);
    }
}

// ---------------- 4. SpMM hop: out = 0.85*A@zin + 0.15*v (+ residual) ----------------
// blockDim (64,4): 4 rows/block. Edge metadata staged in smem (LDS.128 broadcast),
// inner loop issues only the z-gather LDGs.
__global__ __launch_bounds__(256) void spmm_kernel(
    int zin_sel, int out_sel, int resid_sel, const float* __restrict__ resid_ext)
{
    __shared__ __align__(16) float2 sca[4][MAXD];
    int r = threadIdx.y;
    int i = blockIdx.x * 4 + r;          // grid = 750 exactly covers 3000
    int h = threadIdx.x;
    const float* __restrict__ zin = (zin_sel == 0) ? g_z0 : (zin_sel == 1) ? g_z1 : g_v;
    float* __restrict__ outp      = (out_sel == 0) ? g_z0 : (out_sel == 1) ? g_z1 : g_h;
    int degp = g_degp[i];
    // stage this row's packed edges (coalesced float2 loads)
    const float2* __restrict__ cap = &g_ca[i * MAXD];
    for (int s = h; s < degp; s += 64) sca[r][s] = __ldg(&cap[s]);
    __syncthreads();
    const float4* __restrict__ s4 = reinterpret_cast<const float4*>(sca[r]);
    float acc0 = 0.f, acc1 = 0.f;
    for (int s = 0; s < degp; s += 8) {
        int q = s >> 1;
        float4 e01 = s4[q + 0];   // {j0,a0,j1,a1}
        float4 e23 = s4[q + 1];
        float4 e45 = s4[q + 2];
        float4 e67 = s4[q + 3];
        float z0 = __ldg(&zin[__float_as_int(e01.x) + h]);
        float z1 = __ldg(&zin[__float_as_int(e01.z) + h]);
        float z2 = __ldg(&zin[__float_as_int(e23.x) + h]);
        float z3 = __ldg(&zin[__float_as_int(e23.z) + h]);
        float z4 = __ldg(&zin[__float_as_int(e45.x) + h]);
        float z5 = __ldg(&zin[__float_as_int(e45.z) + h]);
        float z6 = __ldg(&zin[__float_as_int(e67.x) + h]);
        float z7 = __ldg(&zin[__float_as_int(e67.z) + h]);
        acc0 += e01.y * z0; acc1 += e01.w * z1;
        acc0 += e23.y * z2; acc1 += e23.w * z3;
        acc0 += e45.y * z4; acc1 += e45.w * z5;
        acc0 += e67.y * z6; acc1 += e67.w * z7;
    }
    float res = 0.85f * (acc0 + acc1) + 0.15f * g_v[i * HID + h];
    if (resid_sel == 1) res += resid_ext[i * HID + h];
    else if (resid_sel == 2) res += g_h[i * HID + h];
    outp[i * HID + h] = res;
}

// ---------------- 5. cluster softmax, ss2, P[g,h], sum(Wp) ----------------
__global__ __launch_bounds__(256) void cluster_kernel(
    const float* __restrict__ Wg, const float* __restrict__ bg, const float* __restrict__ Wp)
{
    __shared__ float sWg[HID * NGRP];
    __shared__ float sbg[NGRP];
    __shared__ float sws[256 * NGRP];
    __shared__ float sred[256];
    int tid = threadIdx.x;
    if (tid < HID * NGRP) sWg[tid] = Wg[tid];
    if (tid < NGRP) sbg[tid] = bg[tid];
    __syncthreads();
    int base = blockIdx.x * 256;
    int n = base + tid;
    float wpv = 0.f, s0 = 0.f, s1 = 0.f, s2 = 0.f, s3 = 0.f;
    if (n < N_NODES) {
        float l0 = sbg[0], l1 = sbg[1], l2 = sbg[2], l3 = sbg[3];
#pragma unroll
        for (int c = 0; c < HID; c++) {
            float hv = g_h[n * HID + c];
            l0 += hv * sWg[c * 4 + 0];
            l1 += hv * sWg[c * 4 + 1];
            l2 += hv * sWg[c * 4 + 2];
            l3 += hv * sWg[c * 4 + 3];
        }
        float m = fmaxf(fmaxf(l0, l1), fmaxf(l2, l3));
        float e0 = __expf(l0 - m), e1 = __expf(l1 - m), e2 = __expf(l2 - m), e3 = __expf(l3 - m);
        float inv = 1.f / (e0 + e1 + e2 + e3);
        s0 = e0 * inv; s1 = e1 * inv; s2 = e2 * inv; s3 = e3 * inv;
        g_ss2[n] = s0 * s0 + s1 * s1 + s2 * s2 + s3 * s3;
        wpv = Wp[n];
    }
    sws[tid * 4 + 0] = s0 * wpv;
    sws[tid * 4 + 1] = s1 * wpv;
    sws[tid * 4 + 2] = s2 * wpv;
    sws[tid * 4 + 3] = s3 * wpv;
    sred[tid] = wpv;
    __syncthreads();
    int g = tid >> 6, h = tid & 63;
    int nv = min(256, N_NODES - base);
    float acc = 0.f;
    for (int nn = 0; nn < nv; nn++)
        acc += sws[nn * 4 + g] * g_h[(base + nn) * HID + h];
    atomicAdd(&g_P[g * HID + h], acc);
    for (int s = 128; s > 0; s >>= 1) {
        __syncthreads();
        if (tid < s) sred[tid] += sred[tid + s];
    }
    __syncthreads();
    if (tid == 0) atomicAdd(&g_P[NGRP * HID], sred[0]);
}

// ---------------- 6. per-user stats + fused epilogue ----------------
__global__ __launch_bounds__(64) void finalize_kernel(
    const int* __restrict__ cate, const float* __restrict__ gamma,
    const float* __restrict__ beta, const float* __restrict__ bp, float* __restrict__ out)
{
    int b = blockIdx.x;
    int h = threadIdx.x;
    float S1 = 0.f, S2 = 0.f;
#pragma unroll 1
    for (int l = 0; l < SEQL; l++) {
        int c = cate[b * SEQL + l];
        if (c != 0) {
            float gv = g_h[c * HID + h];
            S1 += gv;
            S2 += gv * gv * g_ss2[c];
        }
    }
    const float invn = 1.f / (float)(NGRP * SEQL);
    float mean = S1 * invn;
    float var  = S2 * invn - mean * mean;
    float inv  = rsqrtf(var + 1e-5f);
    float ga = gamma[h], be = beta[h];
    float Swp = g_P[NGRP * HID];
    float bpv = bp[0];
    float k1 = inv * ga;
    float addc = be * Swp + bpv;
    float ms = mean * Swp;
#pragma unroll
    for (int g = 0; g < NGRP; g++) {
        out[(b * NGRP + g) * HID + h] = k1 * (g_P[g * HID + h] - ms) + addc;
    }
}

// ---------------- launch ----------------
extern "C" void kernel_launch(void* const* d_in, const int* in_sizes, int n_in,
                              void* d_out, int out_size)
{
    const int*   cate  = (const int*)  d_in[0];
    const float* adj   = (const float*)d_in[1];
    const float* emb   = (const float*)d_in[2];
    const float* Wq    = (const float*)d_in[3];
    const float* Wk    = (const float*)d_in[4];
    const float* Wv    = (const float*)d_in[5];
    const float* Wg    = (const float*)d_in[6];
    const float* bg    = (const float*)d_in[7];
    const float* Wp    = (const float*)d_in[8];
    const float* bp    = (const float*)d_in[9];
    const float* gamma = (const float*)d_in[10];
    const float* beta  = (const float*)d_in[11];
    float* out = (float*)d_out;

    build_csr<<<N_NODES, 128>>>(adj);

    for (int l = 0; l < 2; l++) {
        qkv_kernel<<<(N_NODES + 31) / 32, dim3(64, 8)>>>(
            emb, (l == 0) ? 0 : 1, Wq + l * HID * HID, Wk + l * HID * HID, Wv + l * HID * HID);
        edge_softmax<<<(N_NODES * 32 + 255) / 256, 256>>>();
        spmm_kernel<<<N_NODES / 4, dim3(64, 4)>>>(2, 0, 0, nullptr);           // z0 = f(v)
        spmm_kernel<<<N_NODES / 4, dim3(64, 4)>>>(0, 1, 0, nullptr);           // z1 = f(z0)
        spmm_kernel<<<N_NODES / 4, dim3(64, 4)>>>(1, 0, 0, nullptr);           // z0 = f(z1)
        spmm_kernel<<<N_NODES / 4, dim3(64, 4)>>>(0, 2, (l == 0) ? 1 : 2,
                                                  (l == 0) ? emb : nullptr);   // h = resid + f(z0)
    }

    cluster_kernel<<<(N_NODES + 255) / 256, 256>>>(Wg, bg, Wp);
    finalize_kernel<<<BATCH, HID>>>(cate, gamma, beta, bp, out);
}

// round 5
// speedup vs baseline: 1.1641x; 1.0529x over previous
#include <cuda_runtime.h>
#include <cuda_bf16.h>
#include <math.h>

#define N_NODES   3000
#define HID       64
#define MAXD      128
#define NGRP      4
#define BATCH     256
#define SEQL      50

// ---------------- scratch (device globals; no allocation) ----------------
__device__ int   g_col[N_NODES * MAXD];
__device__ int   g_deg[N_NODES];     // real degree
__device__ int   g_degp[N_NODES];    // padded to multiple of 8
__device__ __align__(16) float2 g_ca[N_NODES * MAXD];  // {.x=bitcast(col*HID), .y=coef}
__device__ __align__(16) float g_q  [N_NODES * HID];
__device__ __align__(16) float g_k  [N_NODES * HID];
__device__ __align__(16) float g_v  [N_NODES * HID];
__device__ __align__(16) float g_z0 [N_NODES * HID];
__device__ __align__(16) float g_z1 [N_NODES * HID];
__device__ __align__(16) float g_h  [N_NODES * HID];
__device__ float g_ss2[N_NODES];
__device__ float g_P  [NGRP * HID + 1];   // [0..255]=P[g,h], [256]=sum(Wp)

// ---------------- 1. build CSR from dense adj (+ zero g_P for this replay) ----------------
__global__ void build_csr(const float* __restrict__ adj) {
    int i = blockIdx.x;
    if (i == 0) {
        for (int t = threadIdx.x; t <= NGRP * HID; t += blockDim.x) g_P[t] = 0.f;
    }
    __shared__ int cnt;
    if (threadIdx.x == 0) cnt = 0;
    __syncthreads();
    const float4* row = reinterpret_cast<const float4*>(adj + (size_t)i * N_NODES);
    for (int j4 = threadIdx.x; j4 < N_NODES / 4; j4 += blockDim.x) {
        float4 f = row[j4];
        int j = j4 * 4;
        if (f.x > 0.f) { int p = atomicAdd(&cnt, 1); if (p < MAXD) g_col[i * MAXD + p] = j; }
        if (f.y > 0.f) { int p = atomicAdd(&cnt, 1); if (p < MAXD) g_col[i * MAXD + p] = j + 1; }
        if (f.z > 0.f) { int p = atomicAdd(&cnt, 1); if (p < MAXD) g_col[i * MAXD + p] = j + 2; }
        if (f.w > 0.f) { int p = atomicAdd(&cnt, 1); if (p < MAXD) g_col[i * MAXD + p] = j + 3; }
    }
    __syncthreads();
    int deg = min(cnt, MAXD);
    int degp = min((deg + 7) & ~7, MAXD);
    if (threadIdx.x == 0) { g_deg[i] = deg; g_degp[i] = degp; }
    for (int p = deg + (int)threadIdx.x; p < degp; p += blockDim.x) g_col[i * MAXD + p] = 0;
}

// ---------------- 2. q/k/v projections ----------------
__global__ __launch_bounds__(512) void qkv_kernel(
    const float* __restrict__ h_ext, int hsel,
    const float* __restrict__ Wq, const float* __restrict__ Wk, const float* __restrict__ Wv)
{
    __shared__ float sW[3][HID * HID];
    const float* hsrc = (hsel == 0) ? h_ext : g_h;
    int tid = threadIdx.y * 64 + threadIdx.x;
    for (int idx = tid; idx < HID * HID; idx += 512) {
        sW[0][idx] = Wq[idx]; sW[1][idx] = Wk[idx]; sW[2][idx] = Wv[idx];
    }
    __syncthreads();
    int t = threadIdx.x;
    int row0 = blockIdx.x * 32;
    for (int rr = threadIdx.y; rr < 32; rr += 8) {
        int gi = row0 + rr;
        if (gi >= N_NODES) continue;
        float aq = 0.f, ak = 0.f, av = 0.f;
        const float* hp = hsrc + gi * HID;
#pragma unroll
        for (int c = 0; c < HID; c++) {
            float hv = __ldg(&hp[c]);
            aq += hv * sW[0][c * 64 + t];
            ak += hv * sW[1][c * 64 + t];
            av += hv * sW[2][c * 64 + t];
        }
        g_q[gi * HID + t] = aq;
        g_k[gi * HID + t] = ak;
        g_v[gi * HID + t] = av;
    }
}

// ---------------- 3. edge scores + row softmax (warp per row, pairwise float4 dot) ----------------
// lanes 0-15 handle edge s, lanes 16-31 edge s+1; each lane loads float4 of k.
__global__ __launch_bounds__(128) void edge_softmax() {
    __shared__ float sdot[4][MAXD];
    int ty = threadIdx.y;
    int i = blockIdx.x * 4 + ty;
    int lane = threadIdx.x;
    int half = lane >> 4;          // 0 or 1
    int hl = lane & 15;            // 0..15
    int deg = g_deg[i];
    int degp = g_degp[i];
    // q fragment for this lane (both halves load the same 4 floats)
    float4 qv = __ldg(reinterpret_cast<const float4*>(&g_q[i * HID + hl * 4]));
    const int* __restrict__ cp = &g_col[i * MAXD];
    for (int s = 0; s < degp; s += 2) {
        int e = s + half;
        int j = __ldg(&cp[e]);     // broadcast within each 16-lane group
        float4 kv = __ldg(reinterpret_cast<const float4*>(&g_k[j * HID + hl * 4]));
        float d = qv.x * kv.x + qv.y * kv.y + qv.z * kv.z + qv.w * kv.w;
        // reduce within 16-lane group
        d += __shfl_xor_sync(0xffffffffu, d, 8);
        d += __shfl_xor_sync(0xffffffffu, d, 4);
        d += __shfl_xor_sync(0xffffffffu, d, 2);
        d += __shfl_xor_sync(0xffffffffu, d, 1);
        if (hl == 0) sdot[ty][e] = d;
    }
    __syncwarp();
    // softmax over this row's dots
    float vals[4];
#pragma unroll
    for (int tpass = 0; tpass < 4; tpass++) {
        int s = lane + 32 * tpass;
        vals[tpass] = (s < deg) ? sdot[ty][s] * 0.125f : -1e30f;
    }
    float m = fmaxf(fmaxf(vals[0], vals[1]), fmaxf(vals[2], vals[3]));
#pragma unroll
    for (int o = 16; o > 0; o >>= 1) m = fmaxf(m, __shfl_xor_sync(0xffffffffu, m, o));
    float sum = 0.f;
#pragma unroll
    for (int tpass = 0; tpass < 4; tpass++) {
        int s = lane + 32 * tpass;
        float e = (s < deg) ? __expf(vals[tpass] - m) : 0.f;
        vals[tpass] = e;
        sum += e;
    }
#pragma unroll
    for (int o = 16; o > 0; o >>= 1) sum += __shfl_xor_sync(0xffffffffu, sum, o);
    float inv = 1.f / sum;
#pragma unroll
    for (int tpass = 0; tpass < 4; tpass++) {
        int s = lane + 32 * tpass;
        if (s < deg)
            g_ca[i * MAXD + s] = make_float2(__int_as_float(__ldg(&cp[s]) * HID), vals[tpass] * inv);
        else if (s < degp)
            g_ca[i * MAXD + s] = make_float2(__int_as_float(0), 0.f);
    }
}

// ---------------- 4. SpMM hop (warp per row, 2 edges per LDG.128) ----------------
__global__ __launch_bounds__(128) void spmm_kernel(
    int zin_sel, int out_sel, int resid_sel, const float* __restrict__ resid_ext)
{
    __shared__ __align__(16) float2 sca[4][MAXD];
    int ty = threadIdx.y;
    int i = blockIdx.x * 4 + ty;         // grid = 750 covers 3000 exactly
    int lane = threadIdx.x;
    int half = lane >> 4;
    int hl = lane & 15;
    int h4 = hl * 4;
    const float* __restrict__ zin = (zin_sel == 0) ? g_z0 : (zin_sel == 1) ? g_z1 : g_v;
    float* __restrict__ outp      = (out_sel == 0) ? g_z0 : (out_sel == 1) ? g_z1 : g_h;
    int degp = g_degp[i];
    // stage this row's packed edges (coalesced float2 loads by this warp)
    const float2* __restrict__ cap = &g_ca[i * MAXD];
    for (int s = lane; s < degp; s += 32) sca[ty][s] = __ldg(&cap[s]);
    __syncwarp();
    const float4* __restrict__ s4 = reinterpret_cast<const float4*>(sca[ty]);
    float ax = 0.f, ay = 0.f, az = 0.f, aw = 0.f;
    for (int s = 0; s < degp; s += 8) {
        int q = s >> 1;
#pragma unroll
        for (int t = 0; t < 4; t++) {
            float4 e2 = s4[q + t];                 // {j_even, a_even, j_odd, a_odd} (broadcast)
            float cj = half ? e2.z : e2.x;
            float cc = half ? e2.w : e2.y;
            int j = __float_as_int(cj);            // pre-multiplied by HID
            float4 z = __ldg(reinterpret_cast<const float4*>(&zin[j + h4]));
            ax += cc * z.x; ay += cc * z.y; az += cc * z.z; aw += cc * z.w;
        }
    }
    // combine halves: lanes 0-15 get lane+16's partial
    ax += __shfl_down_sync(0xffffffffu, ax, 16);
    ay += __shfl_down_sync(0xffffffffu, ay, 16);
    az += __shfl_down_sync(0xffffffffu, az, 16);
    aw += __shfl_down_sync(0xffffffffu, aw, 16);
    if (half == 0) {
        float4 v4 = __ldg(reinterpret_cast<const float4*>(&g_v[i * HID + h4]));
        float4 r;
        r.x = 0.85f * ax + 0.15f * v4.x;
        r.y = 0.85f * ay + 0.15f * v4.y;
        r.z = 0.85f * az + 0.15f * v4.z;
        r.w = 0.85f * aw + 0.15f * v4.w;
        if (resid_sel == 1) {
            float4 e4 = __ldg(reinterpret_cast<const float4*>(&resid_ext[i * HID + h4]));
            r.x += e4.x; r.y += e4.y; r.z += e4.z; r.w += e4.w;
        } else if (resid_sel == 2) {
            float4 e4 = *reinterpret_cast<const float4*>(&g_h[i * HID + h4]);
            r.x += e4.x; r.y += e4.y; r.z += e4.z; r.w += e4.w;
        }
        *reinterpret_cast<float4*>(&outp[i * HID + h4]) = r;
    }
}

// ---------------- 5. cluster softmax, ss2, P[g,h], sum(Wp) ----------------
__global__ __launch_bounds__(256) void cluster_kernel(
    const float* __restrict__ Wg, const float* __restrict__ bg, const float* __restrict__ Wp)
{
    __shared__ float sWg[HID * NGRP];
    __shared__ float sbg[NGRP];
    __shared__ float sws[256 * NGRP];
    __shared__ float sred[256];
    int tid = threadIdx.x;
    if (tid < HID * NGRP) sWg[tid] = Wg[tid];
    if (tid < NGRP) sbg[tid] = bg[tid];
    __syncthreads();
    int base = blockIdx.x * 256;
    int n = base + tid;
    float wpv = 0.f, s0 = 0.f, s1 = 0.f, s2 = 0.f, s3 = 0.f;
    if (n < N_NODES) {
        float l0 = sbg[0], l1 = sbg[1], l2 = sbg[2], l3 = sbg[3];
#pragma unroll
        for (int c = 0; c < HID; c++) {
            float hv = g_h[n * HID + c];
            l0 += hv * sWg[c * 4 + 0];
            l1 += hv * sWg[c * 4 + 1];
            l2 += hv * sWg[c * 4 + 2];
            l3 += hv * sWg[c * 4 + 3];
        }
        float m = fmaxf(fmaxf(l0, l1), fmaxf(l2, l3));
        float e0 = __expf(l0 - m), e1 = __expf(l1 - m), e2 = __expf(l2 - m), e3 = __expf(l3 - m);
        float inv = 1.f / (e0 + e1 + e2 + e3);
        s0 = e0 * inv; s1 = e1 * inv; s2 = e2 * inv; s3 = e3 * inv;
        g_ss2[n] = s0 * s0 + s1 * s1 + s2 * s2 + s3 * s3;
        wpv = Wp[n];
    }
    sws[tid * 4 + 0] = s0 * wpv;
    sws[tid * 4 + 1] = s1 * wpv;
    sws[tid * 4 + 2] = s2 * wpv;
    sws[tid * 4 + 3] = s3 * wpv;
    sred[tid] = wpv;
    __syncthreads();
    int g = tid >> 6, h = tid & 63;
    int nv = min(256, N_NODES - base);
    float acc = 0.f;
    for (int nn = 0; nn < nv; nn++)
        acc += sws[nn * 4 + g] * g_h[(base + nn) * HID + h];
    atomicAdd(&g_P[g * HID + h], acc);
    for (int s = 128; s > 0; s >>= 1) {
        __syncthreads();
        if (tid < s) sred[tid] += sred[tid + s];
    }
    __syncthreads();
    if (tid == 0) atomicAdd(&g_P[NGRP * HID], sred[0]);
}

// ---------------- 6. per-user stats + fused epilogue ----------------
__global__ __launch_bounds__(64) void finalize_kernel(
    const int* __restrict__ cate, const float* __restrict__ gamma,
    const float* __restrict__ beta, const float* __restrict__ bp, float* __restrict__ out)
{
    int b = blockIdx.x;
    int h = threadIdx.x;
    float S1 = 0.f, S2 = 0.f;
#pragma unroll 1
    for (int l = 0; l < SEQL; l++) {
        int c = cate[b * SEQL + l];
        if (c != 0) {
            float gv = g_h[c * HID + h];
            S1 += gv;
            S2 += gv * gv * g_ss2[c];
        }
    }
    const float invn = 1.f / (float)(NGRP * SEQL);
    float mean = S1 * invn;
    float var  = S2 * invn - mean * mean;
    float inv  = rsqrtf(var + 1e-5f);
    float ga = gamma[h], be = beta[h];
    float Swp = g_P[NGRP * HID];
    float bpv = bp[0];
    float k1 = inv * ga;
    float addc = be * Swp + bpv;
    float ms = mean * Swp;
#pragma unroll
    for (int g = 0; g < NGRP; g++) {
        out[(b * NGRP + g) * HID + h] = k1 * (g_P[g * HID + h] - ms) + addc;
    }
}

// ---------------- launch ----------------
extern "C" void kernel_launch(void* const* d_in, const int* in_sizes, int n_in,
                              void* d_out, int out_size)
{
    const int*   cate  = (const int*)  d_in[0];
    const float* adj   = (const float*)d_in[1];
    const float* emb   = (const float*)d_in[2];
    const float* Wq    = (const float*)d_in[3];
    const float* Wk    = (const float*)d_in[4];
    const float* Wv    = (const float*)d_in[5];
    const float* Wg    = (const float*)d_in[6];
    const float* bg    = (const float*)d_in[7];
    const float* Wp    = (const float*)d_in[8];
    const float* bp    = (const float*)d_in[9];
    const float* gamma = (const float*)d_in[10];
    const float* beta  = (const float*)d_in[11];
    float* out = (float*)d_out;

    build_csr<<<N_NODES, 128>>>(adj);

    for (int l = 0; l < 2; l++) {
        qkv_kernel<<<(N_NODES + 31) / 32, dim3(64, 8)>>>(
            emb, (l == 0) ? 0 : 1, Wq + l * HID * HID, Wk + l * HID * HID, Wv + l * HID * HID);
        edge_softmax<<<N_NODES / 4, dim3(32, 4)>>>();
        spmm_kernel<<<N_NODES / 4, dim3(32, 4)>>>(2, 0, 0, nullptr);           // z0 = f(v)
        spmm_kernel<<<N_NODES / 4, dim3(32, 4)>>>(0, 1, 0, nullptr);           // z1 = f(z0)
        spmm_kernel<<<N_NODES / 4, dim3(32, 4)>>>(1, 0, 0, nullptr);           // z0 = f(z1)
        spmm_kernel<<<N_NODES / 4, dim3(32, 4)>>>(0, 2, (l == 0) ? 1 : 2,
                                                  (l == 0) ? emb : nullptr);   // h = resid + f(z0)
    }

    cluster_kernel<<<(N_NODES + 255) / 256, 256>>>(Wg, bg, Wp);
    finalize_kernel<<<BATCH, HID>>>(cate, gamma, beta, bp, out);
}